// round 14
// baseline (speedup 1.0000x reference)
#include <cuda_runtime.h>
#include <cuda_fp16.h>
#include <math.h>

#define NNODE 50000
#define NEDGE 800000
#define E2 (NEDGE + NNODE)
#define HID 128
#define NG 512
#define NCLS 10
#define BN_EPS 1e-5f
#define NEG_SLOPE 0.2f
#define NB_SCAN ((NNODE + 1023) / 1024)

#define TCM 64
#define LDS_PAD 136
#define NT_GEMM ((NNODE + TCM - 1) / TCM)
#define GEMM_GRID 444

// ---------------- device scratch ----------------
__device__ int      g_deg[NNODE];
__device__ int      g_start[NNODE + 1];
__device__ int      g_cursor[NNODE];
__device__ int      g_bsum[64];
__device__ int      g_csr[E2];
__device__ unsigned g_gcount;
__device__ __half   g_bufA[NNODE * HID];
__device__ __half   g_bufB[NNODE * HID];
__device__ __half   g_hh[NNODE * HID];
__device__ float    g_li[NNODE * 4];
__device__ float    g_ri[NNODE * 4];
__device__ __half   g_Wh[4 * HID * HID];
__device__ float    g_Wf4[HID * HID];
__device__ float    g_biasv[5 * HID];
__device__ float    g_pool[NG * HID];
__device__ float    g_tmp[NG * HID];
__device__ float    g_Wct[NCLS * HID];
__device__ float    g_biasc[NCLS];

// ---------------- helpers ----------------
__device__ __forceinline__ unsigned cvta_s(const void* p) {
    return (unsigned)__cvta_generic_to_shared(p);
}
__device__ __forceinline__ void cp_async16(unsigned saddr, const void* gaddr) {
    asm volatile("cp.async.ca.shared.global [%0], [%1], 16;" :: "r"(saddr), "l"(gaddr));
}
__device__ __forceinline__ void cp_async8(unsigned saddr, const void* gaddr) {
    asm volatile("cp.async.ca.shared.global [%0], [%1], 8;" :: "r"(saddr), "l"(gaddr));
}

// ---------------- fused CSR build ----------------
__device__ __forceinline__ void gsync(unsigned phase) {
    __syncthreads();
    if (threadIdx.x == 0) {
        __threadfence();
        atomicAdd(&g_gcount, 1u);
        unsigned target = phase * gridDim.x;
        while (atomicAdd(&g_gcount, 0u) < target) {}
    }
    __syncthreads();
}

__global__ void __launch_bounds__(1024, 1)
k_csr(const int* __restrict__ src, const int* __restrict__ dst,
      int* __restrict__ deg, int* __restrict__ start, int* __restrict__ bsum,
      int* __restrict__ cursor, int* __restrict__ csr) {
    __shared__ int buf[1024];
    int tid = threadIdx.x;
    int bid = blockIdx.x;
    int nthr = gridDim.x * 1024;
    int gt = bid * 1024 + tid;

    for (int e = gt; e < NEDGE; e += nthr) atomicAdd(&deg[dst[e]], 1);
    gsync(1);

    int i = gt;
    int v = 0;
    if (i < NNODE) {
        v = deg[i] + 1;
        deg[i] = 0;
    }
    buf[tid] = v;
    __syncthreads();
    for (int off = 1; off < 1024; off <<= 1) {
        int x = (tid >= off) ? buf[tid - off] : 0;
        __syncthreads();
        buf[tid] += x;
        __syncthreads();
    }
    if (i < NNODE) start[i] = buf[tid] - v;
    if (tid == 1023) bsum[bid] = buf[1023];
    gsync(2);

    if (bid == 0) {
        int bv = 0;
        if (tid < 64) {
            bv = (tid < NB_SCAN) ? bsum[tid] : 0;
            buf[tid] = bv;
        }
        __syncthreads();
        for (int off = 1; off < 64; off <<= 1) {
            int x = (tid < 64 && tid >= off) ? buf[tid - off] : 0;
            __syncthreads();
            if (tid < 64) buf[tid] += x;
            __syncthreads();
        }
        if (tid < NB_SCAN) bsum[tid] = buf[tid] - bv;
    }
    gsync(3);

    if (i < NNODE) {
        int s = start[i] + bsum[bid];
        start[i] = s;
        csr[s] = i;
        cursor[i] = s + 1;
    }
    if (i == 0) start[NNODE] = E2;
    gsync(4);

    for (int e = gt; e < NEDGE; e += nthr) {
        int d = dst[e];
        int p = atomicAdd(&cursor[d], 1);
        csr[p] = src[e];
    }
    __syncthreads();
    if (tid == 0) {
        __threadfence();
        unsigned old = atomicAdd(&g_gcount, 1u);
        if (old == 5u * gridDim.x - 1u) g_gcount = 0;
    }
}

// ---------------- fold all BN into weights (+zero pool/out-tail) ----------------
__global__ void k_fold_all(const float* __restrict__ w_feat, const float* __restrict__ bn_f_g,
                           const float* __restrict__ bn_f_b, const float* __restrict__ b_feat,
                           const float* __restrict__ w_gat, const float* __restrict__ bn_c_g,
                           const float* __restrict__ bn_c_b,
                           const float* __restrict__ w_fc, const float* __restrict__ bn_fc_g,
                           const float* __restrict__ bn_fc_b, const float* __restrict__ b_fc,
                           const float* __restrict__ w_cls, const float* __restrict__ bn_h_g,
                           const float* __restrict__ bn_h_b, const float* __restrict__ b_cls,
                           __half* __restrict__ Wh, float* __restrict__ Wf4,
                           float* __restrict__ biasv,
                           float* __restrict__ Wct, float* __restrict__ biasc,
                           float* __restrict__ pool, float* __restrict__ out, int out_size) {
    int b = blockIdx.x;
    int j = threadIdx.x;
    const float inv = rsqrtf(1.f + BN_EPS);
    if (b < 645) {
        int L = b / 129, r = b % 129;
        const float *W, *gg, *bb, *base;
        if (L == 0)      { W = w_feat; gg = bn_f_g; bb = bn_f_b; base = b_feat; }
        else if (L <= 3) { W = w_gat + (L - 1) * HID * HID; gg = bn_c_g + (L - 1) * HID;
                           bb = bn_c_b + (L - 1) * HID; base = nullptr; }
        else             { W = w_fc; gg = bn_fc_g; bb = bn_fc_b; base = b_fc; }
        if (r < 128) {
            float val = gg[r] * inv * W[r * HID + j];
            if (L < 4) Wh[L * HID * HID + r * HID + j] = __float2half(val);
            else       Wf4[r * HID + j] = val;
        } else {
            float acc = base ? base[j] : 0.f;
            for (int k = 0; k < HID; k++) acc += bb[k] * W[k * HID + j];
            biasv[L * HID + j] = acc;
        }
    } else if (b < 655) {
        int cls = b - 645;
        int k = j;
        float w = w_cls[k * NCLS + cls];
        Wct[cls * HID + k] = bn_h_g[k] * inv * w;
        __shared__ float sred[128];
        sred[k] = bn_h_b[k] * w;
        __syncthreads();
        for (int off = 64; off > 0; off >>= 1) {
            if (k < off) sred[k] += sred[k + off];
            __syncthreads();
        }
        if (k == 0) biasc[cls] = sred[0] + b_cls[cls];
    } else if (b < 1167) {
        int i = (b - 655) * 128 + j;
        if (i < NG * HID) pool[i] = 0.f;
    } else {
        for (int t = NG * NCLS + j; t < out_size; t += 128) out[t] = 0.f;
    }
}

// ---------------- persistent tensor-core GEMM ----------------
__device__ __forceinline__ void prefetch_tile(__half* buf, const __half* A,
                                              int row0, int M, int tid) {
    for (int c = tid; c < TCM * 16; c += 256) {
        int r = c >> 4, q = c & 15;
        if (row0 + r < M)
            cp_async16(cvta_s(&buf[r * LDS_PAD + q * 8]),
                       A + (size_t)(row0 + r) * HID + q * 8);
    }
}

template <int EPI>
__device__ __forceinline__ void tile_compute(
    const __half* __restrict__ sA, const __half* __restrict__ sW,
    const float* __restrict__ sB, const float* __restrict__ sAL,
    const float* __restrict__ sAR,
    __half2* __restrict__ H2, float* __restrict__ li, float* __restrict__ ri,
    int row0, int M, int lane, int warp_m, int warp_n) {
    float c[8][4];
#pragma unroll
    for (int t = 0; t < 8; t++)
#pragma unroll
        for (int q = 0; q < 4; q++) c[t][q] = 0.f;

    int g = lane >> 3;
    int lrow = lane & 7;
    int m_base = warp_m * 16;
    int n_base = warp_n * 64;

#pragma unroll
    for (int k0 = 0; k0 < 128; k0 += 16) {
        unsigned a0, a1, a2, a3;
        {
            int ar = m_base + lrow + ((g & 1) << 3);
            int ac = k0 + ((g >> 1) << 3);
            unsigned addr = cvta_s(&sA[ar * LDS_PAD + ac]);
            asm volatile("ldmatrix.sync.aligned.m8n8.x4.shared.b16 {%0,%1,%2,%3},[%4];"
                         : "=r"(a0), "=r"(a1), "=r"(a2), "=r"(a3) : "r"(addr));
        }
#pragma unroll
        for (int nt = 0; nt < 4; nt++) {
            int n0 = n_base + nt * 16;
            unsigned b0, b1, b2, b3;
            int br = k0 + lrow + ((g & 1) << 3);
            int bc = n0 + ((g >> 1) << 3);
            unsigned addr = cvta_s(&sW[br * LDS_PAD + bc]);
            asm volatile("ldmatrix.sync.aligned.m8n8.x4.trans.shared.b16 {%0,%1,%2,%3},[%4];"
                         : "=r"(b0), "=r"(b1), "=r"(b2), "=r"(b3) : "r"(addr));
            int t0 = nt * 2, t1 = nt * 2 + 1;
            asm volatile("mma.sync.aligned.m16n8k16.row.col.f32.f16.f16.f32 "
                         "{%0,%1,%2,%3},{%4,%5,%6,%7},{%8,%9},{%0,%1,%2,%3};"
                         : "+f"(c[t0][0]), "+f"(c[t0][1]), "+f"(c[t0][2]), "+f"(c[t0][3])
                         : "r"(a0), "r"(a1), "r"(a2), "r"(a3), "r"(b0), "r"(b1));
            asm volatile("mma.sync.aligned.m16n8k16.row.col.f32.f16.f16.f32 "
                         "{%0,%1,%2,%3},{%4,%5,%6,%7},{%8,%9},{%0,%1,%2,%3};"
                         : "+f"(c[t1][0]), "+f"(c[t1][1]), "+f"(c[t1][2]), "+f"(c[t1][3])
                         : "r"(a0), "r"(a1), "r"(a2), "r"(a3), "r"(b2), "r"(b3));
        }
    }

    int r0 = row0 + m_base + (lane >> 2);
    int r1 = r0 + 8;
    float pl0[2] = {0.f, 0.f}, pl1[2] = {0.f, 0.f};
    float pr0[2] = {0.f, 0.f}, pr1[2] = {0.f, 0.f};
#pragma unroll
    for (int t = 0; t < 8; t++) {
        int colg = n_base + t * 8 + ((lane & 3) << 1);
        float b0 = sB[colg], b1 = sB[colg + 1];
        float c0 = c[t][0] + b0, c1 = c[t][1] + b1;
        float c2 = c[t][2] + b0, c3 = c[t][3] + b1;
        if (EPI == 0) {
            c0 = fmaxf(c0, 0.f); c1 = fmaxf(c1, 0.f);
            c2 = fmaxf(c2, 0.f); c3 = fmaxf(c3, 0.f);
        } else {
            int hsel = t >> 2;
            float al0 = sAL[colg], al1 = sAL[colg + 1];
            float ar0 = sAR[colg], ar1 = sAR[colg + 1];
            pl0[hsel] += c0 * al0 + c1 * al1;
            pl1[hsel] += c2 * al0 + c3 * al1;
            pr0[hsel] += c0 * ar0 + c1 * ar1;
            pr1[hsel] += c2 * ar0 + c3 * ar1;
        }
        if (r0 < M) H2[r0 * 64 + (colg >> 1)] = __floats2half2_rn(c0, c1);
        if (r1 < M) H2[r1 * 64 + (colg >> 1)] = __floats2half2_rn(c2, c3);
    }
    if (EPI == 1) {
#pragma unroll
        for (int h = 0; h < 2; h++) {
            pl0[h] += __shfl_xor_sync(0xffffffffu, pl0[h], 1);
            pl0[h] += __shfl_xor_sync(0xffffffffu, pl0[h], 2);
            pl1[h] += __shfl_xor_sync(0xffffffffu, pl1[h], 1);
            pl1[h] += __shfl_xor_sync(0xffffffffu, pl1[h], 2);
            pr0[h] += __shfl_xor_sync(0xffffffffu, pr0[h], 1);
            pr0[h] += __shfl_xor_sync(0xffffffffu, pr0[h], 2);
            pr1[h] += __shfl_xor_sync(0xffffffffu, pr1[h], 1);
            pr1[h] += __shfl_xor_sync(0xffffffffu, pr1[h], 2);
        }
        if ((lane & 3) == 0) {
            int h0 = warp_n * 2, h1 = h0 + 1;
            if (r0 < M) {
                li[r0 * 4 + h0] = pl0[0]; li[r0 * 4 + h1] = pl0[1];
                ri[r0 * 4 + h0] = pr0[0]; ri[r0 * 4 + h1] = pr0[1];
            }
            if (r1 < M) {
                li[r1 * 4 + h0] = pl1[0]; li[r1 * 4 + h1] = pl1[1];
                ri[r1 * 4 + h0] = pr1[0]; ri[r1 * 4 + h1] = pr1[1];
            }
        }
    }
}

template <int A_FP32, int EPI>
__global__ void __launch_bounds__(256)
k_gemm_tc(const void* __restrict__ Ain, const __half* __restrict__ Wh,
          const float* __restrict__ biasv, __half* __restrict__ Hout,
          float* __restrict__ li, float* __restrict__ ri,
          const float* __restrict__ att_l, const float* __restrict__ att_r, int M) {
    extern __shared__ __align__(16) __half smem[];
    __half* sW  = smem;
    __half* sA0 = sW + 128 * LDS_PAD;
    __half* sA1 = sA0 + TCM * LDS_PAD;
    float*  sB  = (float*)(sA1 + TCM * LDS_PAD);
    float*  sAL = sB + 128;
    float*  sAR = sAL + 128;

    int tid = threadIdx.x;
    int lane = tid & 31;
    int wid = tid >> 5;
    int warp_m = wid & 3;
    int warp_n = wid >> 2;
    int ntiles = (M + TCM - 1) / TCM;
    __half2* H2 = (__half2*)Hout;

    for (int idx = tid; idx < 128 * 16; idx += 256) {
        int r = idx >> 4, c8 = idx & 15;
        cp_async16(cvta_s(&sW[r * LDS_PAD + c8 * 8]), Wh + r * HID + c8 * 8);
    }
    if (tid < 128) {
        sB[tid] = __ldg(&biasv[tid]);
        if (EPI == 1) {
            sAL[tid] = __ldg(&att_l[tid]);
            sAR[tid] = __ldg(&att_r[tid]);
        }
    }

    if (A_FP32) {
        asm volatile("cp.async.commit_group;" ::: "memory");
        asm volatile("cp.async.wait_group 0;" ::: "memory");
        __syncthreads();
        const float4* A4 = (const float4*)Ain;
        for (int t = blockIdx.x; t < ntiles; t += gridDim.x) {
            int row0 = t * TCM;
            for (int idx = tid; idx < TCM * 32; idx += 256) {
                int r = idx >> 5, c4 = idx & 31;
                float4 v = make_float4(0.f, 0.f, 0.f, 0.f);
                if (row0 + r < M) v = __ldg(&A4[(row0 + r) * 32 + c4]);
                __half2 h01 = __floats2half2_rn(v.x, v.y);
                __half2 h23 = __floats2half2_rn(v.z, v.w);
                uint2 u;
                u.x = *(unsigned*)&h01;
                u.y = *(unsigned*)&h23;
                *(uint2*)&sA0[r * LDS_PAD + c4 * 4] = u;
            }
            __syncthreads();
            tile_compute<EPI>(sA0, sW, sB, sAL, sAR, H2, li, ri, row0, M,
                              lane, warp_m, warp_n);
            __syncthreads();
        }
    } else {
        const __half* Ah = (const __half*)Ain;
        int t = blockIdx.x;
        if (t < ntiles) prefetch_tile(sA0, Ah, t * TCM, M, tid);
        asm volatile("cp.async.commit_group;" ::: "memory");
        int cursel = 0;
        for (; t < ntiles; t += gridDim.x) {
            asm volatile("cp.async.wait_group 0;" ::: "memory");
            __syncthreads();
            int tn = t + gridDim.x;
            if (tn < ntiles)
                prefetch_tile(cursel ? sA0 : sA1, Ah, tn * TCM, M, tid);
            asm volatile("cp.async.commit_group;" ::: "memory");
            tile_compute<EPI>(cursel ? sA1 : sA0, sW, sB, sAL, sAR, H2, li, ri,
                              t * TCM, M, lane, warp_m, warp_n);
            __syncthreads();
            cursel ^= 1;
        }
    }
}

#define GEMM_SMEM ((128 + 2 * TCM) * LDS_PAD * 2 + 3 * 128 * 4)

// ---------------- shfl helpers ----------------
__device__ __forceinline__ float grp8_sum(float v) {
    v += __shfl_xor_sync(0xffffffffu, v, 1);
    v += __shfl_xor_sync(0xffffffffu, v, 2);
    v += __shfl_xor_sync(0xffffffffu, v, 4);
    return v;
}

// ---------------- attention: warp/node, cp.async smem-pipelined gathers --------------
// per-warp buffer: [0,1024): hj (4 edges x 32 lanes x 8B); [1024,1088): li (4 x 16B)
#define ABUF 1088

__device__ __forceinline__ void att_prefetch(unsigned sb, const __half* __restrict__ hh,
                                             const float* __restrict__ li,
                                             int s0, int s1, int s2, int s3, int lane) {
    cp_async8(sb + 0 * 256 + lane * 8, hh + (size_t)s0 * HID + lane * 4);
    cp_async8(sb + 1 * 256 + lane * 8, hh + (size_t)s1 * HID + lane * 4);
    cp_async8(sb + 2 * 256 + lane * 8, hh + (size_t)s2 * HID + lane * 4);
    cp_async8(sb + 3 * 256 + lane * 8, hh + (size_t)s3 * HID + lane * 4);
    if (lane < 4) {
        int sk = (lane & 2) ? ((lane & 1) ? s3 : s2) : ((lane & 1) ? s1 : s0);
        cp_async16(sb + 1024 + lane * 16, li + (size_t)sk * 4);
    }
    asm volatile("cp.async.commit_group;" ::: "memory");
}

__device__ __forceinline__ float4 rd_h4(const char* buf, int k, int lane) {
    uint2 u = *(const uint2*)(buf + k * 256 + lane * 8);
    __half2 ha = *(__half2*)&u.x;
    __half2 hb = *(__half2*)&u.y;
    float2 f01 = __half22float2(ha);
    float2 f23 = __half22float2(hb);
    return make_float4(f01.x, f01.y, f23.x, f23.y);
}

__device__ __forceinline__ float4 ld_h4g(const uint2* __restrict__ hh2u, int node, int lane) {
    uint2 u = __ldg(&hh2u[node * 32 + lane]);
    __half2 ha = *(__half2*)&u.x;
    __half2 hb = *(__half2*)&u.y;
    float2 f01 = __half22float2(ha);
    float2 f23 = __half22float2(hb);
    return make_float4(f01.x, f01.y, f23.x, f23.y);
}

__device__ __forceinline__ void amerge(float alpha, const float4& hj,
                                       float& m, float& s, float4& acc) {
    alpha = alpha > 0.f ? alpha : NEG_SLOPE * alpha;
    float nm = fmaxf(m, alpha);
    float c = __expf(m - nm);
    float w = __expf(alpha - nm);
    s = s * c + w;
    acc.x = acc.x * c + w * hj.x;
    acc.y = acc.y * c + w * hj.y;
    acc.z = acc.z * c + w * hj.z;
    acc.w = acc.w * c + w * hj.w;
    m = nm;
}

__global__ void __launch_bounds__(256)
k_attn(const __half* __restrict__ hh, const int* __restrict__ start,
       const int* __restrict__ csr, const float* __restrict__ li,
       const float* __restrict__ ri, const float* __restrict__ b_gat,
       __half* __restrict__ out) {
    __shared__ __align__(16) char sbuf[8][2][ABUF];
    int wl = threadIdx.x >> 5;
    int lane = threadIdx.x & 31;
    int warp = (blockIdx.x * blockDim.x + threadIdx.x) >> 5;
    if (warp >= NNODE) return;
    int hq = lane >> 3;
    const uint2* hh2u = (const uint2*)hh;
    float4 hi = ld_h4g(hh2u, warp, lane);
    float rin = __ldg(&ri[warp * 4 + hq]);

    float m = -INFINITY, s = 0.f;
    float4 acc = make_float4(0.f, 0.f, 0.f, 0.f);
    int e0 = start[warp];
    int eend = start[warp + 1];
    int nch = (eend - e0) >> 2;

    unsigned sb0 = cvta_s(sbuf[wl][0]);
    unsigned sb1 = cvta_s(sbuf[wl][1]);
    int i0 = 0, i1 = 0, i2 = 0, i3 = 0;

    if (nch >= 1) {
        i0 = __ldg(&csr[e0 + 0]);
        i1 = __ldg(&csr[e0 + 1]);
        i2 = __ldg(&csr[e0 + 2]);
        i3 = __ldg(&csr[e0 + 3]);
        att_prefetch(sb0, hh, li, i0, i1, i2, i3, lane);
    }
    if (nch >= 2) {
        i0 = __ldg(&csr[e0 + 4]);
        i1 = __ldg(&csr[e0 + 5]);
        i2 = __ldg(&csr[e0 + 6]);
        i3 = __ldg(&csr[e0 + 7]);
        att_prefetch(sb1, hh, li, i0, i1, i2, i3, lane);
        if (nch >= 3) {
            i0 = __ldg(&csr[e0 + 8]);
            i1 = __ldg(&csr[e0 + 9]);
            i2 = __ldg(&csr[e0 + 10]);
            i3 = __ldg(&csr[e0 + 11]);
        }
    }

    for (int ci = 0; ci < nch; ci++) {
        if (ci + 1 < nch) {
            asm volatile("cp.async.wait_group 1;" ::: "memory");
        } else {
            asm volatile("cp.async.wait_group 0;" ::: "memory");
        }
        __syncwarp();
        const char* buf = (ci & 1) ? sbuf[wl][1] : sbuf[wl][0];
        float4 h0 = rd_h4(buf, 0, lane);
        float4 h1 = rd_h4(buf, 1, lane);
        float4 h2 = rd_h4(buf, 2, lane);
        float4 h3 = rd_h4(buf, 3, lane);
        float l0 = *(const float*)(buf + 1024 + 0 * 16 + hq * 4);
        float l1 = *(const float*)(buf + 1024 + 1 * 16 + hq * 4);
        float l2 = *(const float*)(buf + 1024 + 2 * 16 + hq * 4);
        float l3 = *(const float*)(buf + 1024 + 3 * 16 + hq * 4);
        __syncwarp();
        if (ci + 2 < nch) {
            att_prefetch((ci & 1) ? sb1 : sb0, hh, li, i0, i1, i2, i3, lane);
            if (ci + 3 < nch) {
                int base = e0 + (ci + 3) * 4;
                i0 = __ldg(&csr[base + 0]);
                i1 = __ldg(&csr[base + 1]);
                i2 = __ldg(&csr[base + 2]);
                i3 = __ldg(&csr[base + 3]);
            }
        }
        float g0 = grp8_sum(hi.x * h0.x + hi.y * h0.y + hi.z * h0.z + hi.w * h0.w);
        float g1 = grp8_sum(hi.x * h1.x + hi.y * h1.y + hi.z * h1.z + hi.w * h1.w);
        float g2 = grp8_sum(hi.x * h2.x + hi.y * h2.y + hi.z * h2.z + hi.w * h2.w);
        float g3 = grp8_sum(hi.x * h3.x + hi.y * h3.y + hi.z * h3.z + hi.w * h3.w);
        float a0 = __fdividef(l0 + rin, 1.f + __expf(-g0));
        float a1 = __fdividef(l1 + rin, 1.f + __expf(-g1));
        float a2 = __fdividef(l2 + rin, 1.f + __expf(-g2));
        float a3 = __fdividef(l3 + rin, 1.f + __expf(-g3));
        a0 = a0 > 0.f ? a0 : NEG_SLOPE * a0;
        a1 = a1 > 0.f ? a1 : NEG_SLOPE * a1;
        a2 = a2 > 0.f ? a2 : NEG_SLOPE * a2;
        a3 = a3 > 0.f ? a3 : NEG_SLOPE * a3;
        float mc = fmaxf(fmaxf(a0, a1), fmaxf(a2, a3));
        float w0 = __expf(a0 - mc);
        float w1 = __expf(a1 - mc);
        float w2 = __expf(a2 - mc);
        float w3 = __expf(a3 - mc);
        float sc = (w0 + w1) + (w2 + w3);
        float4 ac;
        ac.x = (w0 * h0.x + w1 * h1.x) + (w2 * h2.x + w3 * h3.x);
        ac.y = (w0 * h0.y + w1 * h1.y) + (w2 * h2.y + w3 * h3.y);
        ac.z = (w0 * h0.z + w1 * h1.z) + (w2 * h2.z + w3 * h3.z);
        ac.w = (w0 * h0.w + w1 * h1.w) + (w2 * h2.w + w3 * h3.w);
        float nm = fmaxf(m, mc);
        float cm = __expf(m - nm);
        float cc = __expf(mc - nm);
        s = s * cm + sc * cc;
        acc.x = acc.x * cm + ac.x * cc;
        acc.y = acc.y * cm + ac.y * cc;
        acc.z = acc.z * cm + ac.z * cc;
        acc.w = acc.w * cm + ac.w * cc;
        m = nm;
    }
    for (int e = e0 + nch * 4; e < eend; e++) {
        int sn = __ldg(&csr[e]);
        float4 hj = ld_h4g(hh2u, sn, lane);
        float lg = grp8_sum(hi.x * hj.x + hi.y * hj.y + hi.z * hj.z + hi.w * hj.w);
        float lj = __ldg(&li[sn * 4 + hq]);
        float a = __fdividef(lj + rin, 1.f + __expf(-lg));
        amerge(a, hj, m, s, acc);
    }

    float invs = __fdividef(1.f, s + 1e-16f);
    float4 bg = __ldg(&((const float4*)b_gat)[lane]);
    float ox = fmaxf(acc.x * invs + bg.x, 0.f);
    float oy = fmaxf(acc.y * invs + bg.y, 0.f);
    float oz = fmaxf(acc.z * invs + bg.z, 0.f);
    float ow = fmaxf(acc.w * invs + bg.w, 0.f);
    __half2 o01 = __floats2half2_rn(ox, oy);
    __half2 o23 = __floats2half2_rn(oz, ow);
    uint2 u;
    u.x = *(unsigned*)&o01;
    u.y = *(unsigned*)&o23;
    ((uint2*)out)[warp * 32 + lane] = u;
}

// ---------------- pooling (batch sorted, fp16 input) ----------------
#define PCHUNK 128
__global__ void k_pool(const __half* __restrict__ h, const int* __restrict__ batch,
                       float* __restrict__ g) {
    __shared__ int sb[PCHUNK];
    int c = threadIdx.x;
    int n0 = blockIdx.x * PCHUNK;
    {
        int idx = n0 + c;
        sb[c] = (idx < NNODE) ? batch[idx] : -1;
    }
    __syncthreads();
    if (sb[0] < 0) return;
    float acc = 0.f;
    int cur = sb[0];
    for (int i = 0; i < PCHUNK; i++) {
        int b = sb[i];
        if (b < 0) break;
        if (b != cur) {
            atomicAdd(&g[cur * HID + c], acc);
            acc = 0.f;
            cur = b;
        }
        acc += __half2float(h[(n0 + i) * HID + c]);
    }
    atomicAdd(&g[cur * HID + c], acc);
}

// ---------------- scalar fp32 GEMM for fc (M=512) ----------------
__global__ void k_gemm_fc(const float* __restrict__ A, const float* __restrict__ W,
                          const float* __restrict__ biasv, float* __restrict__ C, int M) {
    __shared__ float sA[8][HID];
    int j = threadIdx.x;
    int row0 = blockIdx.x * 8;
#pragma unroll
    for (int r = 0; r < 8; r++) {
        int rr = row0 + r;
        sA[r][j] = (rr < M) ? A[rr * HID + j] : 0.f;
    }
    __syncthreads();
    float b = biasv[j];
    float acc[8];
#pragma unroll
    for (int r = 0; r < 8; r++) acc[r] = b;
    for (int k = 0; k < HID; k++) {
        float w = __ldg(&W[k * HID + j]);
#pragma unroll
        for (int r = 0; r < 8; r++) acc[r] += sA[r][k] * w;
    }
#pragma unroll
    for (int r = 0; r < 8; r++) {
        int rr = row0 + r;
        if (rr < M) C[rr * HID + j] = fmaxf(acc[r], 0.f);
    }
}

// ---------------- final logits + log_softmax ----------------
__global__ void k_final(const float* __restrict__ t, const float* __restrict__ Wct,
                        const float* __restrict__ bc, float* __restrict__ out) {
    __shared__ float sr[HID];
    int row = blockIdx.x;
    int lane = threadIdx.x;
    for (int i = lane; i < HID; i += 32) sr[i] = t[row * HID + i];
    __syncthreads();
    float lg = -INFINITY;
    if (lane < NCLS) {
        float a = bc[lane];
        const float* wr = Wct + lane * HID;
        for (int k = 0; k < HID; k++) a += sr[k] * wr[k];
        lg = a;
    }
    float mx = lg;
    for (int o = 16; o > 0; o >>= 1) mx = fmaxf(mx, __shfl_xor_sync(0xffffffffu, mx, o));
    float ex = (lane < NCLS) ? __expf(lg - mx) : 0.f;
    float sm = ex;
    for (int o = 16; o > 0; o >>= 1) sm += __shfl_xor_sync(0xffffffffu, sm, o);
    if (lane < NCLS) out[row * NCLS + lane] = lg - mx - logf(sm);
}

// ---------------- launch ----------------
static inline void* sym(const void* s) {
    void* p = nullptr;
    cudaGetSymbolAddress(&p, s);
    return p;
}

extern "C" void kernel_launch(void* const* d_in, const int* in_sizes, int n_in,
                              void* d_out, int out_size) {
    const float* x        = (const float*)d_in[0];
    const int*   ei       = (const int*)d_in[1];
    const int*   batch    = (const int*)d_in[2];
    const float* bn_f_g   = (const float*)d_in[3];
    const float* bn_f_b   = (const float*)d_in[4];
    const float* w_feat   = (const float*)d_in[5];
    const float* b_feat   = (const float*)d_in[6];
    const float* bn_c_g   = (const float*)d_in[7];
    const float* bn_c_b   = (const float*)d_in[8];
    const float* w_gat    = (const float*)d_in[9];
    const float* att_l    = (const float*)d_in[10];
    const float* att_r    = (const float*)d_in[11];
    const float* b_gat    = (const float*)d_in[12];
    const float* bn_fc_g  = (const float*)d_in[13];
    const float* bn_fc_b  = (const float*)d_in[14];
    const float* w_fc     = (const float*)d_in[15];
    const float* b_fc     = (const float*)d_in[16];
    const float* bn_h_g   = (const float*)d_in[17];
    const float* bn_h_b   = (const float*)d_in[18];
    const float* w_cls    = (const float*)d_in[19];
    const float* b_cls    = (const float*)d_in[20];
    float* out = (float*)d_out;

    const int* srcp = ei;
    const int* dstp = ei + NEDGE;

    int*     deg    = (int*)sym(g_deg);
    int*     start  = (int*)sym(g_start);
    int*     cursor = (int*)sym(g_cursor);
    int*     bsum   = (int*)sym(g_bsum);
    int*     csr    = (int*)sym(g_csr);
    __half*  bufA   = (__half*)sym(g_bufA);
    __half*  bufB   = (__half*)sym(g_bufB);
    __half*  hh     = (__half*)sym(g_hh);
    float*   li     = (float*)sym(g_li);
    float*   ri     = (float*)sym(g_ri);
    __half*  Wh     = (__half*)sym(g_Wh);
    float*   Wf4    = (float*)sym(g_Wf4);
    float*   biasv  = (float*)sym(g_biasv);
    float*   pool   = (float*)sym(g_pool);
    float*   tmp    = (float*)sym(g_tmp);
    float*   Wct    = (float*)sym(g_Wct);
    float*   biasc  = (float*)sym(g_biasc);

    static cudaStream_t s2;
    static cudaEvent_t evFork, evJoin;
    static bool init_done = false;
    if (!init_done) {
        cudaFuncSetAttribute(k_gemm_tc<1, 0>, cudaFuncAttributeMaxDynamicSharedMemorySize,
                             GEMM_SMEM);
        cudaFuncSetAttribute(k_gemm_tc<0, 1>, cudaFuncAttributeMaxDynamicSharedMemorySize,
                             GEMM_SMEM);
        cudaStreamCreateWithFlags(&s2, cudaStreamNonBlocking);
        cudaEventCreateWithFlags(&evFork, cudaEventDisableTiming);
        cudaEventCreateWithFlags(&evJoin, cudaEventDisableTiming);
        init_done = true;
    }

    // fork: CSR build runs on s2, overlapping fold + feature GEMM + layer-0 EPI GEMM
    cudaEventRecord(evFork, 0);
    cudaStreamWaitEvent(s2, evFork, 0);
    k_csr<<<NB_SCAN, 1024, 0, s2>>>(srcp, dstp, deg, start, bsum, cursor, csr);
    cudaEventRecord(evJoin, s2);

    k_fold_all<<<1168, 128>>>(w_feat, bn_f_g, bn_f_b, b_feat,
                              w_gat, bn_c_g, bn_c_b,
                              w_fc, bn_fc_g, bn_fc_b, b_fc,
                              w_cls, bn_h_g, bn_h_b, b_cls,
                              Wh, Wf4, biasv, Wct, biasc, pool, out, out_size);

    int gblocks = GEMM_GRID < NT_GEMM ? GEMM_GRID : NT_GEMM;
    k_gemm_tc<1, 0><<<gblocks, 256, GEMM_SMEM>>>(x, Wh, biasv, bufA,
                                                 nullptr, nullptr, nullptr, nullptr,
                                                 NNODE);

    __half* cur = bufA;
    __half* nxt = bufB;
    for (int i = 0; i < 3; i++) {
        int L = 1 + i;
        k_gemm_tc<0, 1><<<gblocks, 256, GEMM_SMEM>>>(cur, Wh + L * HID * HID,
                                                     biasv + L * HID, hh,
                                                     li, ri,
                                                     att_l + i * HID, att_r + i * HID,
                                                     NNODE);
        if (i == 0) cudaStreamWaitEvent(0, evJoin, 0);   // join CSR before first attention
        k_attn<<<(NNODE * 32 + 255) / 256, 256>>>(hh, start, csr, li, ri,
                                                  b_gat + i * HID, nxt);
        __half* t2 = cur; cur = nxt; nxt = t2;
    }

    k_pool<<<(NNODE + PCHUNK - 1) / PCHUNK, HID>>>(cur, batch, pool);

    k_gemm_fc<<<(NG + 7) / 8, HID>>>(pool, Wf4, biasv + 4 * HID, tmp, NG);

    k_final<<<NG, 32>>>(tmp, Wct, biasc, out);
}

// round 15
// speedup vs baseline: 1.0435x; 1.0435x over previous
#include <cuda_runtime.h>
#include <cuda_fp16.h>
#include <math.h>

#define NNODE 50000
#define NEDGE 800000
#define E2 (NEDGE + NNODE)
#define HID 128
#define NG 512
#define NCLS 10
#define BN_EPS 1e-5f
#define NEG_SLOPE 0.2f
#define NB_SCAN ((NNODE + 1023) / 1024)

#define TCM 64
#define LDS_PAD 136
#define NT_GEMM ((NNODE + TCM - 1) / TCM)
#define GEMM_GRID 444

// ---------------- device scratch ----------------
__device__ int      g_deg[NNODE];
__device__ int      g_start[NNODE + 1];
__device__ int      g_cursor[NNODE];
__device__ int      g_bsum[64];
__device__ int      g_csr[E2];
__device__ unsigned g_gcount;
__device__ __half   g_bufA[NNODE * HID];
__device__ __half   g_bufB[NNODE * HID];
__device__ __half   g_hh[NNODE * HID];
__device__ float    g_li[NNODE * 4];
__device__ float    g_ri[NNODE * 4];
__device__ __half   g_Wh[4 * HID * HID];
__device__ float    g_Wf4[HID * HID];
__device__ float    g_biasv[5 * HID];
__device__ float    g_pool[NG * HID];
__device__ float    g_tmp[NG * HID];
__device__ float    g_Wct[NCLS * HID];
__device__ float    g_biasc[NCLS];

// ---------------- fused CSR build ----------------
__device__ __forceinline__ void gsync(unsigned phase) {
    __syncthreads();
    if (threadIdx.x == 0) {
        __threadfence();
        atomicAdd(&g_gcount, 1u);
        unsigned target = phase * gridDim.x;
        while (atomicAdd(&g_gcount, 0u) < target) {}
    }
    __syncthreads();
}

__global__ void __launch_bounds__(1024, 1)
k_csr(const int* __restrict__ src, const int* __restrict__ dst,
      int* __restrict__ deg, int* __restrict__ start, int* __restrict__ bsum,
      int* __restrict__ cursor, int* __restrict__ csr) {
    __shared__ int buf[1024];
    int tid = threadIdx.x;
    int bid = blockIdx.x;
    int nthr = gridDim.x * 1024;
    int gt = bid * 1024 + tid;

    for (int e = gt; e < NEDGE; e += nthr) atomicAdd(&deg[dst[e]], 1);
    gsync(1);

    int i = gt;
    int v = 0;
    if (i < NNODE) {
        v = deg[i] + 1;
        deg[i] = 0;
    }
    buf[tid] = v;
    __syncthreads();
    for (int off = 1; off < 1024; off <<= 1) {
        int x = (tid >= off) ? buf[tid - off] : 0;
        __syncthreads();
        buf[tid] += x;
        __syncthreads();
    }
    if (i < NNODE) start[i] = buf[tid] - v;
    if (tid == 1023) bsum[bid] = buf[1023];
    gsync(2);

    if (bid == 0) {
        int bv = 0;
        if (tid < 64) {
            bv = (tid < NB_SCAN) ? bsum[tid] : 0;
            buf[tid] = bv;
        }
        __syncthreads();
        for (int off = 1; off < 64; off <<= 1) {
            int x = (tid < 64 && tid >= off) ? buf[tid - off] : 0;
            __syncthreads();
            if (tid < 64) buf[tid] += x;
            __syncthreads();
        }
        if (tid < NB_SCAN) bsum[tid] = buf[tid] - bv;
    }
    gsync(3);

    if (i < NNODE) {
        int s = start[i] + bsum[bid];
        start[i] = s;
        csr[s] = i;
        cursor[i] = s + 1;
    }
    if (i == 0) start[NNODE] = E2;
    gsync(4);

    for (int e = gt; e < NEDGE; e += nthr) {
        int d = dst[e];
        int p = atomicAdd(&cursor[d], 1);
        csr[p] = src[e];
    }
    __syncthreads();
    if (tid == 0) {
        __threadfence();
        unsigned old = atomicAdd(&g_gcount, 1u);
        if (old == 5u * gridDim.x - 1u) g_gcount = 0;
    }
}

// ---------------- fold all BN into weights (+zero pool/out-tail) ----------------
__global__ void k_fold_all(const float* __restrict__ w_feat, const float* __restrict__ bn_f_g,
                           const float* __restrict__ bn_f_b, const float* __restrict__ b_feat,
                           const float* __restrict__ w_gat, const float* __restrict__ bn_c_g,
                           const float* __restrict__ bn_c_b,
                           const float* __restrict__ w_fc, const float* __restrict__ bn_fc_g,
                           const float* __restrict__ bn_fc_b, const float* __restrict__ b_fc,
                           const float* __restrict__ w_cls, const float* __restrict__ bn_h_g,
                           const float* __restrict__ bn_h_b, const float* __restrict__ b_cls,
                           __half* __restrict__ Wh, float* __restrict__ Wf4,
                           float* __restrict__ biasv,
                           float* __restrict__ Wct, float* __restrict__ biasc,
                           float* __restrict__ pool, float* __restrict__ out, int out_size) {
    int b = blockIdx.x;
    int j = threadIdx.x;
    const float inv = rsqrtf(1.f + BN_EPS);
    if (b < 645) {
        int L = b / 129, r = b % 129;
        const float *W, *gg, *bb, *base;
        if (L == 0)      { W = w_feat; gg = bn_f_g; bb = bn_f_b; base = b_feat; }
        else if (L <= 3) { W = w_gat + (L - 1) * HID * HID; gg = bn_c_g + (L - 1) * HID;
                           bb = bn_c_b + (L - 1) * HID; base = nullptr; }
        else             { W = w_fc; gg = bn_fc_g; bb = bn_fc_b; base = b_fc; }
        if (r < 128) {
            float val = gg[r] * inv * W[r * HID + j];
            if (L < 4) Wh[L * HID * HID + r * HID + j] = __float2half(val);
            else       Wf4[r * HID + j] = val;
        } else {
            float acc = base ? base[j] : 0.f;
            for (int k = 0; k < HID; k++) acc += bb[k] * W[k * HID + j];
            biasv[L * HID + j] = acc;
        }
    } else if (b < 655) {
        int cls = b - 645;
        int k = j;
        float w = w_cls[k * NCLS + cls];
        Wct[cls * HID + k] = bn_h_g[k] * inv * w;
        __shared__ float sred[128];
        sred[k] = bn_h_b[k] * w;
        __syncthreads();
        for (int off = 64; off > 0; off >>= 1) {
            if (k < off) sred[k] += sred[k + off];
            __syncthreads();
        }
        if (k == 0) biasc[cls] = sred[0] + b_cls[cls];
    } else if (b < 1167) {
        int i = (b - 655) * 128 + j;
        if (i < NG * HID) pool[i] = 0.f;
    } else {
        for (int t = NG * NCLS + j; t < out_size; t += 128) out[t] = 0.f;
    }
}

// ---------------- persistent tensor-core GEMM ----------------
__device__ __forceinline__ unsigned cvta_s(const void* p) {
    return (unsigned)__cvta_generic_to_shared(p);
}
__device__ __forceinline__ void cp_async16(unsigned saddr, const void* gaddr) {
    asm volatile("cp.async.ca.shared.global [%0], [%1], 16;" :: "r"(saddr), "l"(gaddr));
}

__device__ __forceinline__ void prefetch_tile(__half* buf, const __half* A,
                                              int row0, int M, int tid) {
    for (int c = tid; c < TCM * 16; c += 256) {
        int r = c >> 4, q = c & 15;
        if (row0 + r < M)
            cp_async16(cvta_s(&buf[r * LDS_PAD + q * 8]),
                       A + (size_t)(row0 + r) * HID + q * 8);
    }
}

template <int EPI>
__device__ __forceinline__ void tile_compute(
    const __half* __restrict__ sA, const __half* __restrict__ sW,
    const float* __restrict__ sB, const float* __restrict__ sAL,
    const float* __restrict__ sAR,
    __half2* __restrict__ H2, float* __restrict__ li, float* __restrict__ ri,
    int row0, int M, int lane, int warp_m, int warp_n) {
    float c[8][4];
#pragma unroll
    for (int t = 0; t < 8; t++)
#pragma unroll
        for (int q = 0; q < 4; q++) c[t][q] = 0.f;

    int g = lane >> 3;
    int lrow = lane & 7;
    int m_base = warp_m * 16;
    int n_base = warp_n * 64;

#pragma unroll
    for (int k0 = 0; k0 < 128; k0 += 16) {
        unsigned a0, a1, a2, a3;
        {
            int ar = m_base + lrow + ((g & 1) << 3);
            int ac = k0 + ((g >> 1) << 3);
            unsigned addr = cvta_s(&sA[ar * LDS_PAD + ac]);
            asm volatile("ldmatrix.sync.aligned.m8n8.x4.shared.b16 {%0,%1,%2,%3},[%4];"
                         : "=r"(a0), "=r"(a1), "=r"(a2), "=r"(a3) : "r"(addr));
        }
#pragma unroll
        for (int nt = 0; nt < 4; nt++) {
            int n0 = n_base + nt * 16;
            unsigned b0, b1, b2, b3;
            int br = k0 + lrow + ((g & 1) << 3);
            int bc = n0 + ((g >> 1) << 3);
            unsigned addr = cvta_s(&sW[br * LDS_PAD + bc]);
            asm volatile("ldmatrix.sync.aligned.m8n8.x4.trans.shared.b16 {%0,%1,%2,%3},[%4];"
                         : "=r"(b0), "=r"(b1), "=r"(b2), "=r"(b3) : "r"(addr));
            int t0 = nt * 2, t1 = nt * 2 + 1;
            asm volatile("mma.sync.aligned.m16n8k16.row.col.f32.f16.f16.f32 "
                         "{%0,%1,%2,%3},{%4,%5,%6,%7},{%8,%9},{%0,%1,%2,%3};"
                         : "+f"(c[t0][0]), "+f"(c[t0][1]), "+f"(c[t0][2]), "+f"(c[t0][3])
                         : "r"(a0), "r"(a1), "r"(a2), "r"(a3), "r"(b0), "r"(b1));
            asm volatile("mma.sync.aligned.m16n8k16.row.col.f32.f16.f16.f32 "
                         "{%0,%1,%2,%3},{%4,%5,%6,%7},{%8,%9},{%0,%1,%2,%3};"
                         : "+f"(c[t1][0]), "+f"(c[t1][1]), "+f"(c[t1][2]), "+f"(c[t1][3])
                         : "r"(a0), "r"(a1), "r"(a2), "r"(a3), "r"(b2), "r"(b3));
        }
    }

    int r0 = row0 + m_base + (lane >> 2);
    int r1 = r0 + 8;
    float pl0[2] = {0.f, 0.f}, pl1[2] = {0.f, 0.f};
    float pr0[2] = {0.f, 0.f}, pr1[2] = {0.f, 0.f};
#pragma unroll
    for (int t = 0; t < 8; t++) {
        int colg = n_base + t * 8 + ((lane & 3) << 1);
        float b0 = sB[colg], b1 = sB[colg + 1];
        float c0 = c[t][0] + b0, c1 = c[t][1] + b1;
        float c2 = c[t][2] + b0, c3 = c[t][3] + b1;
        if (EPI == 0) {
            c0 = fmaxf(c0, 0.f); c1 = fmaxf(c1, 0.f);
            c2 = fmaxf(c2, 0.f); c3 = fmaxf(c3, 0.f);
        } else {
            int hsel = t >> 2;
            float al0 = sAL[colg], al1 = sAL[colg + 1];
            float ar0 = sAR[colg], ar1 = sAR[colg + 1];
            pl0[hsel] += c0 * al0 + c1 * al1;
            pl1[hsel] += c2 * al0 + c3 * al1;
            pr0[hsel] += c0 * ar0 + c1 * ar1;
            pr1[hsel] += c2 * ar0 + c3 * ar1;
        }
        if (r0 < M) H2[r0 * 64 + (colg >> 1)] = __floats2half2_rn(c0, c1);
        if (r1 < M) H2[r1 * 64 + (colg >> 1)] = __floats2half2_rn(c2, c3);
    }
    if (EPI == 1) {
#pragma unroll
        for (int h = 0; h < 2; h++) {
            pl0[h] += __shfl_xor_sync(0xffffffffu, pl0[h], 1);
            pl0[h] += __shfl_xor_sync(0xffffffffu, pl0[h], 2);
            pl1[h] += __shfl_xor_sync(0xffffffffu, pl1[h], 1);
            pl1[h] += __shfl_xor_sync(0xffffffffu, pl1[h], 2);
            pr0[h] += __shfl_xor_sync(0xffffffffu, pr0[h], 1);
            pr0[h] += __shfl_xor_sync(0xffffffffu, pr0[h], 2);
            pr1[h] += __shfl_xor_sync(0xffffffffu, pr1[h], 1);
            pr1[h] += __shfl_xor_sync(0xffffffffu, pr1[h], 2);
        }
        if ((lane & 3) == 0) {
            int h0 = warp_n * 2, h1 = h0 + 1;
            if (r0 < M) {
                li[r0 * 4 + h0] = pl0[0]; li[r0 * 4 + h1] = pl0[1];
                ri[r0 * 4 + h0] = pr0[0]; ri[r0 * 4 + h1] = pr0[1];
            }
            if (r1 < M) {
                li[r1 * 4 + h0] = pl1[0]; li[r1 * 4 + h1] = pl1[1];
                ri[r1 * 4 + h0] = pr1[0]; ri[r1 * 4 + h1] = pr1[1];
            }
        }
    }
}

template <int A_FP32, int EPI>
__global__ void __launch_bounds__(256)
k_gemm_tc(const void* __restrict__ Ain, const __half* __restrict__ Wh,
          const float* __restrict__ biasv, __half* __restrict__ Hout,
          float* __restrict__ li, float* __restrict__ ri,
          const float* __restrict__ att_l, const float* __restrict__ att_r, int M) {
    extern __shared__ __align__(16) __half smem[];
    __half* sW  = smem;
    __half* sA0 = sW + 128 * LDS_PAD;
    __half* sA1 = sA0 + TCM * LDS_PAD;
    float*  sB  = (float*)(sA1 + TCM * LDS_PAD);
    float*  sAL = sB + 128;
    float*  sAR = sAL + 128;

    int tid = threadIdx.x;
    int lane = tid & 31;
    int wid = tid >> 5;
    int warp_m = wid & 3;
    int warp_n = wid >> 2;
    int ntiles = (M + TCM - 1) / TCM;
    __half2* H2 = (__half2*)Hout;

    for (int idx = tid; idx < 128 * 16; idx += 256) {
        int r = idx >> 4, c8 = idx & 15;
        cp_async16(cvta_s(&sW[r * LDS_PAD + c8 * 8]), Wh + r * HID + c8 * 8);
    }
    if (tid < 128) {
        sB[tid] = __ldg(&biasv[tid]);
        if (EPI == 1) {
            sAL[tid] = __ldg(&att_l[tid]);
            sAR[tid] = __ldg(&att_r[tid]);
        }
    }

    if (A_FP32) {
        asm volatile("cp.async.commit_group;" ::: "memory");
        asm volatile("cp.async.wait_group 0;" ::: "memory");
        __syncthreads();
        const float4* A4 = (const float4*)Ain;
        for (int t = blockIdx.x; t < ntiles; t += gridDim.x) {
            int row0 = t * TCM;
            for (int idx = tid; idx < TCM * 32; idx += 256) {
                int r = idx >> 5, c4 = idx & 31;
                float4 v = make_float4(0.f, 0.f, 0.f, 0.f);
                if (row0 + r < M) v = __ldg(&A4[(row0 + r) * 32 + c4]);
                __half2 h01 = __floats2half2_rn(v.x, v.y);
                __half2 h23 = __floats2half2_rn(v.z, v.w);
                uint2 u;
                u.x = *(unsigned*)&h01;
                u.y = *(unsigned*)&h23;
                *(uint2*)&sA0[r * LDS_PAD + c4 * 4] = u;
            }
            __syncthreads();
            tile_compute<EPI>(sA0, sW, sB, sAL, sAR, H2, li, ri, row0, M,
                              lane, warp_m, warp_n);
            __syncthreads();
        }
    } else {
        const __half* Ah = (const __half*)Ain;
        int t = blockIdx.x;
        if (t < ntiles) prefetch_tile(sA0, Ah, t * TCM, M, tid);
        asm volatile("cp.async.commit_group;" ::: "memory");
        int cursel = 0;
        for (; t < ntiles; t += gridDim.x) {
            asm volatile("cp.async.wait_group 0;" ::: "memory");
            __syncthreads();
            int tn = t + gridDim.x;
            if (tn < ntiles)
                prefetch_tile(cursel ? sA0 : sA1, Ah, tn * TCM, M, tid);
            asm volatile("cp.async.commit_group;" ::: "memory");
            tile_compute<EPI>(cursel ? sA1 : sA0, sW, sB, sAL, sAR, H2, li, ri,
                              t * TCM, M, lane, warp_m, warp_n);
            __syncthreads();
            cursel ^= 1;
        }
    }
}

#define GEMM_SMEM ((128 + 2 * TCM) * LDS_PAD * 2 + 3 * 128 * 4)

// ---------------- shfl helpers ----------------
__device__ __forceinline__ float grp8_sum(float v) {
    v += __shfl_xor_sync(0xffffffffu, v, 1);
    v += __shfl_xor_sync(0xffffffffu, v, 2);
    v += __shfl_xor_sync(0xffffffffu, v, 4);
    return v;
}

// ---------------- attention: warp per dst node, 4-edge chunks + idx prefetch ---------
__device__ __forceinline__ float4 ld_h4(const uint2* __restrict__ hh2u, int node, int lane) {
    uint2 u = __ldg(&hh2u[node * 32 + lane]);
    __half2 ha = *(__half2*)&u.x;
    __half2 hb = *(__half2*)&u.y;
    float2 f01 = __half22float2(ha);
    float2 f23 = __half22float2(hb);
    return make_float4(f01.x, f01.y, f23.x, f23.y);
}

__device__ __forceinline__ void amerge(float alpha, const float4& hj,
                                       float& m, float& s, float4& acc) {
    alpha = alpha > 0.f ? alpha : NEG_SLOPE * alpha;
    // single-exp merge: only the smaller side gets scaled
    if (alpha <= m) {
        float w = __expf(alpha - m);
        s += w;
        acc.x += w * hj.x;
        acc.y += w * hj.y;
        acc.z += w * hj.z;
        acc.w += w * hj.w;
    } else {
        float cm = (m == -INFINITY) ? 0.f : __expf(m - alpha);
        s = s * cm + 1.f;
        acc.x = acc.x * cm + hj.x;
        acc.y = acc.y * cm + hj.y;
        acc.z = acc.z * cm + hj.z;
        acc.w = acc.w * cm + hj.w;
        m = alpha;
    }
}

__global__ void __launch_bounds__(256)
k_attn(const __half* __restrict__ hh, const int* __restrict__ start,
       const int* __restrict__ csr, const float* __restrict__ li,
       const float* __restrict__ ri, const float* __restrict__ b_gat,
       __half* __restrict__ out) {
    int warp = (blockIdx.x * blockDim.x + threadIdx.x) >> 5;
    int lane = threadIdx.x & 31;
    if (warp >= NNODE) return;
    int hq = lane >> 3;
    const uint2* hh2u = (const uint2*)hh;
    float4 hi = ld_h4(hh2u, warp, lane);
    float rin = __ldg(&ri[warp * 4 + hq]);

    float m = -INFINITY, s = 0.f;
    float4 acc = make_float4(0.f, 0.f, 0.f, 0.f);
    int e = start[warp];
    int eend = start[warp + 1];
    int efin = e + ((eend - e) & ~3);

    int i0 = 0, i1 = 0, i2 = 0, i3 = 0;
    if (e < efin) {
        i0 = __ldg(&csr[e + 0]);
        i1 = __ldg(&csr[e + 1]);
        i2 = __ldg(&csr[e + 2]);
        i3 = __ldg(&csr[e + 3]);
    }
    for (; e < efin;) {
        int s0 = i0, s1 = i1, s2 = i2, s3 = i3;
        e += 4;
        if (e < efin) {
            i0 = __ldg(&csr[e + 0]);
            i1 = __ldg(&csr[e + 1]);
            i2 = __ldg(&csr[e + 2]);
            i3 = __ldg(&csr[e + 3]);
        }
        float4 h0 = ld_h4(hh2u, s0, lane);
        float4 h1 = ld_h4(hh2u, s1, lane);
        float4 h2 = ld_h4(hh2u, s2, lane);
        float4 h3 = ld_h4(hh2u, s3, lane);
        float l0 = __ldg(&li[s0 * 4 + hq]);
        float l1 = __ldg(&li[s1 * 4 + hq]);
        float l2 = __ldg(&li[s2 * 4 + hq]);
        float l3 = __ldg(&li[s3 * 4 + hq]);
        float g0 = grp8_sum(hi.x * h0.x + hi.y * h0.y + hi.z * h0.z + hi.w * h0.w);
        float g1 = grp8_sum(hi.x * h1.x + hi.y * h1.y + hi.z * h1.z + hi.w * h1.w);
        float g2 = grp8_sum(hi.x * h2.x + hi.y * h2.y + hi.z * h2.z + hi.w * h2.w);
        float g3 = grp8_sum(hi.x * h3.x + hi.y * h3.y + hi.z * h3.z + hi.w * h3.w);
        float a0 = __fdividef(l0 + rin, 1.f + __expf(-g0));
        float a1 = __fdividef(l1 + rin, 1.f + __expf(-g1));
        float a2 = __fdividef(l2 + rin, 1.f + __expf(-g2));
        float a3 = __fdividef(l3 + rin, 1.f + __expf(-g3));
        a0 = a0 > 0.f ? a0 : NEG_SLOPE * a0;
        a1 = a1 > 0.f ? a1 : NEG_SLOPE * a1;
        a2 = a2 > 0.f ? a2 : NEG_SLOPE * a2;
        a3 = a3 > 0.f ? a3 : NEG_SLOPE * a3;
        float mc = fmaxf(fmaxf(a0, a1), fmaxf(a2, a3));
        float w0 = __expf(a0 - mc);
        float w1 = __expf(a1 - mc);
        float w2 = __expf(a2 - mc);
        float w3 = __expf(a3 - mc);
        float sc = (w0 + w1) + (w2 + w3);
        float4 ac;
        ac.x = (w0 * h0.x + w1 * h1.x) + (w2 * h2.x + w3 * h3.x);
        ac.y = (w0 * h0.y + w1 * h1.y) + (w2 * h2.y + w3 * h3.y);
        ac.z = (w0 * h0.z + w1 * h1.z) + (w2 * h2.z + w3 * h3.z);
        ac.w = (w0 * h0.w + w1 * h1.w) + (w2 * h2.w + w3 * h3.w);
        // single-exp merge with running state (branch is 8-lane-group uniform)
        if (mc <= m) {
            float cc = __expf(mc - m);
            s += sc * cc;
            acc.x += ac.x * cc;
            acc.y += ac.y * cc;
            acc.z += ac.z * cc;
            acc.w += ac.w * cc;
        } else {
            float cm = (m == -INFINITY) ? 0.f : __expf(m - mc);
            s = s * cm + sc;
            acc.x = acc.x * cm + ac.x;
            acc.y = acc.y * cm + ac.y;
            acc.z = acc.z * cm + ac.z;
            acc.w = acc.w * cm + ac.w;
            m = mc;
        }
    }
    for (; e < eend; e++) {
        int sn = __ldg(&csr[e]);
        float4 hj = ld_h4(hh2u, sn, lane);
        float lg = grp8_sum(hi.x * hj.x + hi.y * hj.y + hi.z * hj.z + hi.w * hj.w);
        float lj = __ldg(&li[sn * 4 + hq]);
        float a = __fdividef(lj + rin, 1.f + __expf(-lg));
        amerge(a, hj, m, s, acc);
    }

    float invs = __fdividef(1.f, s + 1e-16f);
    float4 bg = __ldg(&((const float4*)b_gat)[lane]);
    float ox = fmaxf(acc.x * invs + bg.x, 0.f);
    float oy = fmaxf(acc.y * invs + bg.y, 0.f);
    float oz = fmaxf(acc.z * invs + bg.z, 0.f);
    float ow = fmaxf(acc.w * invs + bg.w, 0.f);
    __half2 o01 = __floats2half2_rn(ox, oy);
    __half2 o23 = __floats2half2_rn(oz, ow);
    uint2 u;
    u.x = *(unsigned*)&o01;
    u.y = *(unsigned*)&o23;
    ((uint2*)out)[warp * 32 + lane] = u;
}

// ---------------- pooling (batch sorted, fp16 input) ----------------
#define PCHUNK 128
__global__ void k_pool(const __half* __restrict__ h, const int* __restrict__ batch,
                       float* __restrict__ g) {
    __shared__ int sb[PCHUNK];
    int c = threadIdx.x;
    int n0 = blockIdx.x * PCHUNK;
    {
        int idx = n0 + c;
        sb[c] = (idx < NNODE) ? batch[idx] : -1;
    }
    __syncthreads();
    if (sb[0] < 0) return;
    float acc = 0.f;
    int cur = sb[0];
    for (int i = 0; i < PCHUNK; i++) {
        int b = sb[i];
        if (b < 0) break;
        if (b != cur) {
            atomicAdd(&g[cur * HID + c], acc);
            acc = 0.f;
            cur = b;
        }
        acc += __half2float(h[(n0 + i) * HID + c]);
    }
    atomicAdd(&g[cur * HID + c], acc);
}

// ---------------- scalar fp32 GEMM for fc (M=512) ----------------
__global__ void k_gemm_fc(const float* __restrict__ A, const float* __restrict__ W,
                          const float* __restrict__ biasv, float* __restrict__ C, int M) {
    __shared__ float sA[8][HID];
    int j = threadIdx.x;
    int row0 = blockIdx.x * 8;
#pragma unroll
    for (int r = 0; r < 8; r++) {
        int rr = row0 + r;
        sA[r][j] = (rr < M) ? A[rr * HID + j] : 0.f;
    }
    __syncthreads();
    float b = biasv[j];
    float acc[8];
#pragma unroll
    for (int r = 0; r < 8; r++) acc[r] = b;
    for (int k = 0; k < HID; k++) {
        float w = __ldg(&W[k * HID + j]);
#pragma unroll
        for (int r = 0; r < 8; r++) acc[r] += sA[r][k] * w;
    }
#pragma unroll
    for (int r = 0; r < 8; r++) {
        int rr = row0 + r;
        if (rr < M) C[rr * HID + j] = fmaxf(acc[r], 0.f);
    }
}

// ---------------- final logits + log_softmax ----------------
__global__ void k_final(const float* __restrict__ t, const float* __restrict__ Wct,
                        const float* __restrict__ bc, float* __restrict__ out) {
    __shared__ float sr[HID];
    int row = blockIdx.x;
    int lane = threadIdx.x;
    for (int i = lane; i < HID; i += 32) sr[i] = t[row * HID + i];
    __syncthreads();
    float lg = -INFINITY;
    if (lane < NCLS) {
        float a = bc[lane];
        const float* wr = Wct + lane * HID;
        for (int k = 0; k < HID; k++) a += sr[k] * wr[k];
        lg = a;
    }
    float mx = lg;
    for (int o = 16; o > 0; o >>= 1) mx = fmaxf(mx, __shfl_xor_sync(0xffffffffu, mx, o));
    float ex = (lane < NCLS) ? __expf(lg - mx) : 0.f;
    float sm = ex;
    for (int o = 16; o > 0; o >>= 1) sm += __shfl_xor_sync(0xffffffffu, sm, o);
    if (lane < NCLS) out[row * NCLS + lane] = lg - mx - logf(sm);
}

// ---------------- launch ----------------
static inline void* sym(const void* s) {
    void* p = nullptr;
    cudaGetSymbolAddress(&p, s);
    return p;
}

extern "C" void kernel_launch(void* const* d_in, const int* in_sizes, int n_in,
                              void* d_out, int out_size) {
    const float* x        = (const float*)d_in[0];
    const int*   ei       = (const int*)d_in[1];
    const int*   batch    = (const int*)d_in[2];
    const float* bn_f_g   = (const float*)d_in[3];
    const float* bn_f_b   = (const float*)d_in[4];
    const float* w_feat   = (const float*)d_in[5];
    const float* b_feat   = (const float*)d_in[6];
    const float* bn_c_g   = (const float*)d_in[7];
    const float* bn_c_b   = (const float*)d_in[8];
    const float* w_gat    = (const float*)d_in[9];
    const float* att_l    = (const float*)d_in[10];
    const float* att_r    = (const float*)d_in[11];
    const float* b_gat    = (const float*)d_in[12];
    const float* bn_fc_g  = (const float*)d_in[13];
    const float* bn_fc_b  = (const float*)d_in[14];
    const float* w_fc     = (const float*)d_in[15];
    const float* b_fc     = (const float*)d_in[16];
    const float* bn_h_g   = (const float*)d_in[17];
    const float* bn_h_b   = (const float*)d_in[18];
    const float* w_cls    = (const float*)d_in[19];
    const float* b_cls    = (const float*)d_in[20];
    float* out = (float*)d_out;

    const int* srcp = ei;
    const int* dstp = ei + NEDGE;

    int*     deg    = (int*)sym(g_deg);
    int*     start  = (int*)sym(g_start);
    int*     cursor = (int*)sym(g_cursor);
    int*     bsum   = (int*)sym(g_bsum);
    int*     csr    = (int*)sym(g_csr);
    __half*  bufA   = (__half*)sym(g_bufA);
    __half*  bufB   = (__half*)sym(g_bufB);
    __half*  hh     = (__half*)sym(g_hh);
    float*   li     = (float*)sym(g_li);
    float*   ri     = (float*)sym(g_ri);
    __half*  Wh     = (__half*)sym(g_Wh);
    float*   Wf4    = (float*)sym(g_Wf4);
    float*   biasv  = (float*)sym(g_biasv);
    float*   pool   = (float*)sym(g_pool);
    float*   tmp    = (float*)sym(g_tmp);
    float*   Wct    = (float*)sym(g_Wct);
    float*   biasc  = (float*)sym(g_biasc);

    static cudaStream_t s2;
    static cudaEvent_t evFork, evJoin;
    static bool init_done = false;
    if (!init_done) {
        cudaFuncSetAttribute(k_gemm_tc<1, 0>, cudaFuncAttributeMaxDynamicSharedMemorySize,
                             GEMM_SMEM);
        cudaFuncSetAttribute(k_gemm_tc<0, 1>, cudaFuncAttributeMaxDynamicSharedMemorySize,
                             GEMM_SMEM);
        cudaStreamCreateWithFlags(&s2, cudaStreamNonBlocking);
        cudaEventCreateWithFlags(&evFork, cudaEventDisableTiming);
        cudaEventCreateWithFlags(&evJoin, cudaEventDisableTiming);
        init_done = true;
    }

    // fork: CSR build runs on s2, overlapping fold + feature GEMM + layer-0 EPI GEMM
    cudaEventRecord(evFork, 0);
    cudaStreamWaitEvent(s2, evFork, 0);
    k_csr<<<NB_SCAN, 1024, 0, s2>>>(srcp, dstp, deg, start, bsum, cursor, csr);
    cudaEventRecord(evJoin, s2);

    k_fold_all<<<1168, 128>>>(w_feat, bn_f_g, bn_f_b, b_feat,
                              w_gat, bn_c_g, bn_c_b,
                              w_fc, bn_fc_g, bn_fc_b, b_fc,
                              w_cls, bn_h_g, bn_h_b, b_cls,
                              Wh, Wf4, biasv, Wct, biasc, pool, out, out_size);

    int gblocks = GEMM_GRID < NT_GEMM ? GEMM_GRID : NT_GEMM;
    k_gemm_tc<1, 0><<<gblocks, 256, GEMM_SMEM>>>(x, Wh, biasv, bufA,
                                                 nullptr, nullptr, nullptr, nullptr,
                                                 NNODE);

    __half* cur = bufA;
    __half* nxt = bufB;
    for (int i = 0; i < 3; i++) {
        int L = 1 + i;
        k_gemm_tc<0, 1><<<gblocks, 256, GEMM_SMEM>>>(cur, Wh + L * HID * HID,
                                                     biasv + L * HID, hh,
                                                     li, ri,
                                                     att_l + i * HID, att_r + i * HID,
                                                     NNODE);
        if (i == 0) cudaStreamWaitEvent(0, evJoin, 0);   // join CSR before first attention
        k_attn<<<(NNODE * 32 + 255) / 256, 256>>>(hh, start, csr, li, ri,
                                                  b_gat + i * HID, nxt);
        __half* t2 = cur; cur = nxt; nxt = t2;
    }

    k_pool<<<(NNODE + PCHUNK - 1) / PCHUNK, HID>>>(cur, batch, pool);

    k_gemm_fc<<<(NG + 7) / 8, HID>>>(pool, Wf4, biasv + 4 * HID, tmp, NG);

    k_final<<<NG, 32>>>(tmp, Wct, biasc, out);
}

// round 16
// speedup vs baseline: 1.1164x; 1.0698x over previous
#include <cuda_runtime.h>
#include <cuda_fp16.h>
#include <math.h>

#define NNODE 50000
#define NEDGE 800000
#define E2 (NEDGE + NNODE)
#define HID 128
#define NG 512
#define NCLS 10
#define BN_EPS 1e-5f
#define NEG_SLOPE 0.2f
#define NB_SCAN ((NNODE + 1023) / 1024)

#define TCM 64
#define LDS_PAD 136
#define NT_GEMM ((NNODE + TCM - 1) / TCM)
#define GEMM_GRID 444

// ---------------- device scratch ----------------
__device__ int      g_deg[NNODE];
__device__ int      g_start[NNODE + 1];
__device__ int      g_cursor[NNODE];
__device__ int      g_bsum[64];
__device__ int      g_csr[E2];
__device__ unsigned g_gcount;
__device__ __half   g_bufA[NNODE * HID];
__device__ __half   g_bufB[NNODE * HID];
__device__ __half   g_hh[NNODE * HID];
__device__ float    g_li[NNODE * 4];
__device__ float    g_ri[NNODE * 4];
__device__ __half   g_Wh[4 * HID * HID];
__device__ float    g_Wf4[HID * HID];
__device__ float    g_biasv[5 * HID];
__device__ float    g_pool[NG * HID];
__device__ float    g_tmp[NG * HID];
__device__ float    g_Wct[NCLS * HID];
__device__ float    g_biasc[NCLS];

// ---------------- fused CSR build ----------------
__device__ __forceinline__ void gsync(unsigned phase) {
    __syncthreads();
    if (threadIdx.x == 0) {
        __threadfence();
        atomicAdd(&g_gcount, 1u);
        unsigned target = phase * gridDim.x;
        while (atomicAdd(&g_gcount, 0u) < target) {}
    }
    __syncthreads();
}

__global__ void __launch_bounds__(1024, 1)
k_csr(const int* __restrict__ src, const int* __restrict__ dst,
      int* __restrict__ deg, int* __restrict__ start, int* __restrict__ bsum,
      int* __restrict__ cursor, int* __restrict__ csr) {
    __shared__ int buf[1024];
    int tid = threadIdx.x;
    int bid = blockIdx.x;
    int nthr = gridDim.x * 1024;
    int gt = bid * 1024 + tid;

    for (int e = gt; e < NEDGE; e += nthr) atomicAdd(&deg[dst[e]], 1);
    gsync(1);

    int i = gt;
    int v = 0;
    if (i < NNODE) {
        v = deg[i] + 1;
        deg[i] = 0;
    }
    buf[tid] = v;
    __syncthreads();
    for (int off = 1; off < 1024; off <<= 1) {
        int x = (tid >= off) ? buf[tid - off] : 0;
        __syncthreads();
        buf[tid] += x;
        __syncthreads();
    }
    if (i < NNODE) start[i] = buf[tid] - v;
    if (tid == 1023) bsum[bid] = buf[1023];
    gsync(2);

    if (bid == 0) {
        int bv = 0;
        if (tid < 64) {
            bv = (tid < NB_SCAN) ? bsum[tid] : 0;
            buf[tid] = bv;
        }
        __syncthreads();
        for (int off = 1; off < 64; off <<= 1) {
            int x = (tid < 64 && tid >= off) ? buf[tid - off] : 0;
            __syncthreads();
            if (tid < 64) buf[tid] += x;
            __syncthreads();
        }
        if (tid < NB_SCAN) bsum[tid] = buf[tid] - bv;
    }
    gsync(3);

    if (i < NNODE) {
        int s = start[i] + bsum[bid];
        start[i] = s;
        csr[s] = i;
        cursor[i] = s + 1;
    }
    if (i == 0) start[NNODE] = E2;
    gsync(4);

    for (int e = gt; e < NEDGE; e += nthr) {
        int d = dst[e];
        int p = atomicAdd(&cursor[d], 1);
        csr[p] = src[e];
    }
    __syncthreads();
    if (tid == 0) {
        __threadfence();
        unsigned old = atomicAdd(&g_gcount, 1u);
        if (old == 5u * gridDim.x - 1u) g_gcount = 0;
    }
}

// ---------------- fold all BN into weights (+zero pool/out-tail) ----------------
__global__ void k_fold_all(const float* __restrict__ w_feat, const float* __restrict__ bn_f_g,
                           const float* __restrict__ bn_f_b, const float* __restrict__ b_feat,
                           const float* __restrict__ w_gat, const float* __restrict__ bn_c_g,
                           const float* __restrict__ bn_c_b,
                           const float* __restrict__ w_fc, const float* __restrict__ bn_fc_g,
                           const float* __restrict__ bn_fc_b, const float* __restrict__ b_fc,
                           const float* __restrict__ w_cls, const float* __restrict__ bn_h_g,
                           const float* __restrict__ bn_h_b, const float* __restrict__ b_cls,
                           __half* __restrict__ Wh, float* __restrict__ Wf4,
                           float* __restrict__ biasv,
                           float* __restrict__ Wct, float* __restrict__ biasc,
                           float* __restrict__ pool, float* __restrict__ out, int out_size) {
    int b = blockIdx.x;
    int j = threadIdx.x;
    const float inv = rsqrtf(1.f + BN_EPS);
    if (b < 645) {
        int L = b / 129, r = b % 129;
        const float *W, *gg, *bb, *base;
        if (L == 0)      { W = w_feat; gg = bn_f_g; bb = bn_f_b; base = b_feat; }
        else if (L <= 3) { W = w_gat + (L - 1) * HID * HID; gg = bn_c_g + (L - 1) * HID;
                           bb = bn_c_b + (L - 1) * HID; base = nullptr; }
        else             { W = w_fc; gg = bn_fc_g; bb = bn_fc_b; base = b_fc; }
        if (r < 128) {
            float val = gg[r] * inv * W[r * HID + j];
            if (L < 4) Wh[L * HID * HID + r * HID + j] = __float2half(val);
            else       Wf4[r * HID + j] = val;
        } else {
            float acc = base ? base[j] : 0.f;
            for (int k = 0; k < HID; k++) acc += bb[k] * W[k * HID + j];
            biasv[L * HID + j] = acc;
        }
    } else if (b < 655) {
        int cls = b - 645;
        int k = j;
        float w = w_cls[k * NCLS + cls];
        Wct[cls * HID + k] = bn_h_g[k] * inv * w;
        __shared__ float sred[128];
        sred[k] = bn_h_b[k] * w;
        __syncthreads();
        for (int off = 64; off > 0; off >>= 1) {
            if (k < off) sred[k] += sred[k + off];
            __syncthreads();
        }
        if (k == 0) biasc[cls] = sred[0] + b_cls[cls];
    } else if (b < 1167) {
        int i = (b - 655) * 128 + j;
        if (i < NG * HID) pool[i] = 0.f;
    } else {
        for (int t = NG * NCLS + j; t < out_size; t += 128) out[t] = 0.f;
    }
}

// ---------------- persistent tensor-core GEMM ----------------
__device__ __forceinline__ unsigned cvta_s(const void* p) {
    return (unsigned)__cvta_generic_to_shared(p);
}
__device__ __forceinline__ void cp_async16(unsigned saddr, const void* gaddr) {
    asm volatile("cp.async.ca.shared.global [%0], [%1], 16;" :: "r"(saddr), "l"(gaddr));
}

__device__ __forceinline__ void prefetch_tile(__half* buf, const __half* A,
                                              int row0, int M, int tid) {
    for (int c = tid; c < TCM * 16; c += 256) {
        int r = c >> 4, q = c & 15;
        if (row0 + r < M)
            cp_async16(cvta_s(&buf[r * LDS_PAD + q * 8]),
                       A + (size_t)(row0 + r) * HID + q * 8);
    }
}

template <int EPI>
__device__ __forceinline__ void tile_compute(
    const __half* __restrict__ sA, const __half* __restrict__ sW,
    const float* __restrict__ sB, const float* __restrict__ sAL,
    const float* __restrict__ sAR,
    __half2* __restrict__ H2, float* __restrict__ li, float* __restrict__ ri,
    int row0, int M, int lane, int warp_m, int warp_n) {
    float c[8][4];
#pragma unroll
    for (int t = 0; t < 8; t++)
#pragma unroll
        for (int q = 0; q < 4; q++) c[t][q] = 0.f;

    int g = lane >> 3;
    int lrow = lane & 7;
    int m_base = warp_m * 16;
    int n_base = warp_n * 64;

#pragma unroll
    for (int k0 = 0; k0 < 128; k0 += 16) {
        unsigned a0, a1, a2, a3;
        {
            int ar = m_base + lrow + ((g & 1) << 3);
            int ac = k0 + ((g >> 1) << 3);
            unsigned addr = cvta_s(&sA[ar * LDS_PAD + ac]);
            asm volatile("ldmatrix.sync.aligned.m8n8.x4.shared.b16 {%0,%1,%2,%3},[%4];"
                         : "=r"(a0), "=r"(a1), "=r"(a2), "=r"(a3) : "r"(addr));
        }
#pragma unroll
        for (int nt = 0; nt < 4; nt++) {
            int n0 = n_base + nt * 16;
            unsigned b0, b1, b2, b3;
            int br = k0 + lrow + ((g & 1) << 3);
            int bc = n0 + ((g >> 1) << 3);
            unsigned addr = cvta_s(&sW[br * LDS_PAD + bc]);
            asm volatile("ldmatrix.sync.aligned.m8n8.x4.trans.shared.b16 {%0,%1,%2,%3},[%4];"
                         : "=r"(b0), "=r"(b1), "=r"(b2), "=r"(b3) : "r"(addr));
            int t0 = nt * 2, t1 = nt * 2 + 1;
            asm volatile("mma.sync.aligned.m16n8k16.row.col.f32.f16.f16.f32 "
                         "{%0,%1,%2,%3},{%4,%5,%6,%7},{%8,%9},{%0,%1,%2,%3};"
                         : "+f"(c[t0][0]), "+f"(c[t0][1]), "+f"(c[t0][2]), "+f"(c[t0][3])
                         : "r"(a0), "r"(a1), "r"(a2), "r"(a3), "r"(b0), "r"(b1));
            asm volatile("mma.sync.aligned.m16n8k16.row.col.f32.f16.f16.f32 "
                         "{%0,%1,%2,%3},{%4,%5,%6,%7},{%8,%9},{%0,%1,%2,%3};"
                         : "+f"(c[t1][0]), "+f"(c[t1][1]), "+f"(c[t1][2]), "+f"(c[t1][3])
                         : "r"(a0), "r"(a1), "r"(a2), "r"(a3), "r"(b2), "r"(b3));
        }
    }

    int r0 = row0 + m_base + (lane >> 2);
    int r1 = r0 + 8;
    float pl0[2] = {0.f, 0.f}, pl1[2] = {0.f, 0.f};
    float pr0[2] = {0.f, 0.f}, pr1[2] = {0.f, 0.f};
#pragma unroll
    for (int t = 0; t < 8; t++) {
        int colg = n_base + t * 8 + ((lane & 3) << 1);
        float b0 = sB[colg], b1 = sB[colg + 1];
        float c0 = c[t][0] + b0, c1 = c[t][1] + b1;
        float c2 = c[t][2] + b0, c3 = c[t][3] + b1;
        if (EPI == 0) {
            c0 = fmaxf(c0, 0.f); c1 = fmaxf(c1, 0.f);
            c2 = fmaxf(c2, 0.f); c3 = fmaxf(c3, 0.f);
        } else {
            int hsel = t >> 2;
            float al0 = sAL[colg], al1 = sAL[colg + 1];
            float ar0 = sAR[colg], ar1 = sAR[colg + 1];
            pl0[hsel] += c0 * al0 + c1 * al1;
            pl1[hsel] += c2 * al0 + c3 * al1;
            pr0[hsel] += c0 * ar0 + c1 * ar1;
            pr1[hsel] += c2 * ar0 + c3 * ar1;
        }
        if (r0 < M) H2[r0 * 64 + (colg >> 1)] = __floats2half2_rn(c0, c1);
        if (r1 < M) H2[r1 * 64 + (colg >> 1)] = __floats2half2_rn(c2, c3);
    }
    if (EPI == 1) {
#pragma unroll
        for (int h = 0; h < 2; h++) {
            pl0[h] += __shfl_xor_sync(0xffffffffu, pl0[h], 1);
            pl0[h] += __shfl_xor_sync(0xffffffffu, pl0[h], 2);
            pl1[h] += __shfl_xor_sync(0xffffffffu, pl1[h], 1);
            pl1[h] += __shfl_xor_sync(0xffffffffu, pl1[h], 2);
            pr0[h] += __shfl_xor_sync(0xffffffffu, pr0[h], 1);
            pr0[h] += __shfl_xor_sync(0xffffffffu, pr0[h], 2);
            pr1[h] += __shfl_xor_sync(0xffffffffu, pr1[h], 1);
            pr1[h] += __shfl_xor_sync(0xffffffffu, pr1[h], 2);
        }
        if ((lane & 3) == 0) {
            int h0 = warp_n * 2, h1 = h0 + 1;
            if (r0 < M) {
                li[r0 * 4 + h0] = pl0[0]; li[r0 * 4 + h1] = pl0[1];
                ri[r0 * 4 + h0] = pr0[0]; ri[r0 * 4 + h1] = pr0[1];
            }
            if (r1 < M) {
                li[r1 * 4 + h0] = pl1[0]; li[r1 * 4 + h1] = pl1[1];
                ri[r1 * 4 + h0] = pr1[0]; ri[r1 * 4 + h1] = pr1[1];
            }
        }
    }
}

template <int A_FP32, int EPI>
__global__ void __launch_bounds__(256)
k_gemm_tc(const void* __restrict__ Ain, const __half* __restrict__ Wh,
          const float* __restrict__ biasv, __half* __restrict__ Hout,
          float* __restrict__ li, float* __restrict__ ri,
          const float* __restrict__ att_l, const float* __restrict__ att_r, int M) {
    extern __shared__ __align__(16) __half smem[];
    __half* sW  = smem;
    __half* sA0 = sW + 128 * LDS_PAD;
    __half* sA1 = sA0 + TCM * LDS_PAD;
    float*  sB  = (float*)(sA1 + TCM * LDS_PAD);
    float*  sAL = sB + 128;
    float*  sAR = sAL + 128;

    int tid = threadIdx.x;
    int lane = tid & 31;
    int wid = tid >> 5;
    int warp_m = wid & 3;
    int warp_n = wid >> 2;
    int ntiles = (M + TCM - 1) / TCM;
    __half2* H2 = (__half2*)Hout;

    for (int idx = tid; idx < 128 * 16; idx += 256) {
        int r = idx >> 4, c8 = idx & 15;
        cp_async16(cvta_s(&sW[r * LDS_PAD + c8 * 8]), Wh + r * HID + c8 * 8);
    }
    if (tid < 128) {
        sB[tid] = __ldg(&biasv[tid]);
        if (EPI == 1) {
            sAL[tid] = __ldg(&att_l[tid]);
            sAR[tid] = __ldg(&att_r[tid]);
        }
    }

    if (A_FP32) {
        asm volatile("cp.async.commit_group;" ::: "memory");
        asm volatile("cp.async.wait_group 0;" ::: "memory");
        __syncthreads();
        const float4* A4 = (const float4*)Ain;
        for (int t = blockIdx.x; t < ntiles; t += gridDim.x) {
            int row0 = t * TCM;
            for (int idx = tid; idx < TCM * 32; idx += 256) {
                int r = idx >> 5, c4 = idx & 31;
                float4 v = make_float4(0.f, 0.f, 0.f, 0.f);
                if (row0 + r < M) v = __ldg(&A4[(row0 + r) * 32 + c4]);
                __half2 h01 = __floats2half2_rn(v.x, v.y);
                __half2 h23 = __floats2half2_rn(v.z, v.w);
                uint2 u;
                u.x = *(unsigned*)&h01;
                u.y = *(unsigned*)&h23;
                *(uint2*)&sA0[r * LDS_PAD + c4 * 4] = u;
            }
            __syncthreads();
            tile_compute<EPI>(sA0, sW, sB, sAL, sAR, H2, li, ri, row0, M,
                              lane, warp_m, warp_n);
            __syncthreads();
        }
    } else {
        const __half* Ah = (const __half*)Ain;
        int t = blockIdx.x;
        if (t < ntiles) prefetch_tile(sA0, Ah, t * TCM, M, tid);
        asm volatile("cp.async.commit_group;" ::: "memory");
        int cursel = 0;
        for (; t < ntiles; t += gridDim.x) {
            asm volatile("cp.async.wait_group 0;" ::: "memory");
            __syncthreads();
            int tn = t + gridDim.x;
            if (tn < ntiles)
                prefetch_tile(cursel ? sA0 : sA1, Ah, tn * TCM, M, tid);
            asm volatile("cp.async.commit_group;" ::: "memory");
            tile_compute<EPI>(cursel ? sA1 : sA0, sW, sB, sAL, sAR, H2, li, ri,
                              t * TCM, M, lane, warp_m, warp_n);
            __syncthreads();
            cursel ^= 1;
        }
    }
}

#define GEMM_SMEM ((128 + 2 * TCM) * LDS_PAD * 2 + 3 * 128 * 4)

// ---------------- shfl helpers ----------------
__device__ __forceinline__ float grp8_sum(float v) {
    v += __shfl_xor_sync(0xffffffffu, v, 1);
    v += __shfl_xor_sync(0xffffffffu, v, 2);
    v += __shfl_xor_sync(0xffffffffu, v, 4);
    return v;
}

// ---------------- attention: warp per dst node, unnormalized softmax -----------------
// alpha = leaky_relu((lj+ri)*sigmoid(g)) is O(1)-bounded => direct exp is safe in fp32.
__device__ __forceinline__ float4 ld_h4(const uint2* __restrict__ hh2u, int node, int lane) {
    uint2 u = __ldg(&hh2u[node * 32 + lane]);
    __half2 ha = *(__half2*)&u.x;
    __half2 hb = *(__half2*)&u.y;
    float2 f01 = __half22float2(ha);
    float2 f23 = __half22float2(hb);
    return make_float4(f01.x, f01.y, f23.x, f23.y);
}

__global__ void __launch_bounds__(256)
k_attn(const __half* __restrict__ hh, const int* __restrict__ start,
       const int* __restrict__ csr, const float* __restrict__ li,
       const float* __restrict__ ri, const float* __restrict__ b_gat,
       __half* __restrict__ out) {
    int warp = (blockIdx.x * blockDim.x + threadIdx.x) >> 5;
    int lane = threadIdx.x & 31;
    if (warp >= NNODE) return;
    int hq = lane >> 3;
    const uint2* hh2u = (const uint2*)hh;
    float4 hi = ld_h4(hh2u, warp, lane);
    float rin = __ldg(&ri[warp * 4 + hq]);

    float s = 0.f;
    float4 acc = make_float4(0.f, 0.f, 0.f, 0.f);
    int e = start[warp];
    int eend = start[warp + 1];
    int efin = e + ((eend - e) & ~3);

    int i0 = 0, i1 = 0, i2 = 0, i3 = 0;
    if (e < efin) {
        i0 = __ldg(&csr[e + 0]);
        i1 = __ldg(&csr[e + 1]);
        i2 = __ldg(&csr[e + 2]);
        i3 = __ldg(&csr[e + 3]);
    }
    for (; e < efin;) {
        int s0 = i0, s1 = i1, s2 = i2, s3 = i3;
        e += 4;
        if (e < efin) {
            i0 = __ldg(&csr[e + 0]);
            i1 = __ldg(&csr[e + 1]);
            i2 = __ldg(&csr[e + 2]);
            i3 = __ldg(&csr[e + 3]);
        }
        float4 h0 = ld_h4(hh2u, s0, lane);
        float4 h1 = ld_h4(hh2u, s1, lane);
        float4 h2 = ld_h4(hh2u, s2, lane);
        float4 h3 = ld_h4(hh2u, s3, lane);
        float l0 = __ldg(&li[s0 * 4 + hq]);
        float l1 = __ldg(&li[s1 * 4 + hq]);
        float l2 = __ldg(&li[s2 * 4 + hq]);
        float l3 = __ldg(&li[s3 * 4 + hq]);
        float g0 = grp8_sum(hi.x * h0.x + hi.y * h0.y + hi.z * h0.z + hi.w * h0.w);
        float g1 = grp8_sum(hi.x * h1.x + hi.y * h1.y + hi.z * h1.z + hi.w * h1.w);
        float g2 = grp8_sum(hi.x * h2.x + hi.y * h2.y + hi.z * h2.z + hi.w * h2.w);
        float g3 = grp8_sum(hi.x * h3.x + hi.y * h3.y + hi.z * h3.z + hi.w * h3.w);
        float a0 = __fdividef(l0 + rin, 1.f + __expf(-g0));
        float a1 = __fdividef(l1 + rin, 1.f + __expf(-g1));
        float a2 = __fdividef(l2 + rin, 1.f + __expf(-g2));
        float a3 = __fdividef(l3 + rin, 1.f + __expf(-g3));
        a0 = a0 > 0.f ? a0 : NEG_SLOPE * a0;
        a1 = a1 > 0.f ? a1 : NEG_SLOPE * a1;
        a2 = a2 > 0.f ? a2 : NEG_SLOPE * a2;
        a3 = a3 > 0.f ? a3 : NEG_SLOPE * a3;
        float w0 = __expf(a0);
        float w1 = __expf(a1);
        float w2 = __expf(a2);
        float w3 = __expf(a3);
        s += ((w0 + w1) + (w2 + w3));
        acc.x += (w0 * h0.x + w1 * h1.x) + (w2 * h2.x + w3 * h3.x);
        acc.y += (w0 * h0.y + w1 * h1.y) + (w2 * h2.y + w3 * h3.y);
        acc.z += (w0 * h0.z + w1 * h1.z) + (w2 * h2.z + w3 * h3.z);
        acc.w += (w0 * h0.w + w1 * h1.w) + (w2 * h2.w + w3 * h3.w);
    }
    for (; e < eend; e++) {
        int sn = __ldg(&csr[e]);
        float4 hj = ld_h4(hh2u, sn, lane);
        float lg = grp8_sum(hi.x * hj.x + hi.y * hj.y + hi.z * hj.z + hi.w * hj.w);
        float lj = __ldg(&li[sn * 4 + hq]);
        float a = __fdividef(lj + rin, 1.f + __expf(-lg));
        a = a > 0.f ? a : NEG_SLOPE * a;
        float w = __expf(a);
        s += w;
        acc.x += w * hj.x;
        acc.y += w * hj.y;
        acc.z += w * hj.z;
        acc.w += w * hj.w;
    }

    float invs = __fdividef(1.f, s + 1e-16f);
    float4 bg = __ldg(&((const float4*)b_gat)[lane]);
    float ox = fmaxf(acc.x * invs + bg.x, 0.f);
    float oy = fmaxf(acc.y * invs + bg.y, 0.f);
    float oz = fmaxf(acc.z * invs + bg.z, 0.f);
    float ow = fmaxf(acc.w * invs + bg.w, 0.f);
    __half2 o01 = __floats2half2_rn(ox, oy);
    __half2 o23 = __floats2half2_rn(oz, ow);
    uint2 u;
    u.x = *(unsigned*)&o01;
    u.y = *(unsigned*)&o23;
    ((uint2*)out)[warp * 32 + lane] = u;
}

// ---------------- pooling (batch sorted, fp16 input) ----------------
#define PCHUNK 128
__global__ void k_pool(const __half* __restrict__ h, const int* __restrict__ batch,
                       float* __restrict__ g) {
    __shared__ int sb[PCHUNK];
    int c = threadIdx.x;
    int n0 = blockIdx.x * PCHUNK;
    {
        int idx = n0 + c;
        sb[c] = (idx < NNODE) ? batch[idx] : -1;
    }
    __syncthreads();
    if (sb[0] < 0) return;
    float acc = 0.f;
    int cur = sb[0];
    for (int i = 0; i < PCHUNK; i++) {
        int b = sb[i];
        if (b < 0) break;
        if (b != cur) {
            atomicAdd(&g[cur * HID + c], acc);
            acc = 0.f;
            cur = b;
        }
        acc += __half2float(h[(n0 + i) * HID + c]);
    }
    atomicAdd(&g[cur * HID + c], acc);
}

// ---------------- scalar fp32 GEMM for fc (M=512) ----------------
__global__ void k_gemm_fc(const float* __restrict__ A, const float* __restrict__ W,
                          const float* __restrict__ biasv, float* __restrict__ C, int M) {
    __shared__ float sA[8][HID];
    int j = threadIdx.x;
    int row0 = blockIdx.x * 8;
#pragma unroll
    for (int r = 0; r < 8; r++) {
        int rr = row0 + r;
        sA[r][j] = (rr < M) ? A[rr * HID + j] : 0.f;
    }
    __syncthreads();
    float b = biasv[j];
    float acc[8];
#pragma unroll
    for (int r = 0; r < 8; r++) acc[r] = b;
    for (int k = 0; k < HID; k++) {
        float w = __ldg(&W[k * HID + j]);
#pragma unroll
        for (int r = 0; r < 8; r++) acc[r] += sA[r][k] * w;
    }
#pragma unroll
    for (int r = 0; r < 8; r++) {
        int rr = row0 + r;
        if (rr < M) C[rr * HID + j] = fmaxf(acc[r], 0.f);
    }
}

// ---------------- final logits + log_softmax ----------------
__global__ void k_final(const float* __restrict__ t, const float* __restrict__ Wct,
                        const float* __restrict__ bc, float* __restrict__ out) {
    __shared__ float sr[HID];
    int row = blockIdx.x;
    int lane = threadIdx.x;
    for (int i = lane; i < HID; i += 32) sr[i] = t[row * HID + i];
    __syncthreads();
    float lg = -INFINITY;
    if (lane < NCLS) {
        float a = bc[lane];
        const float* wr = Wct + lane * HID;
        for (int k = 0; k < HID; k++) a += sr[k] * wr[k];
        lg = a;
    }
    float mx = lg;
    for (int o = 16; o > 0; o >>= 1) mx = fmaxf(mx, __shfl_xor_sync(0xffffffffu, mx, o));
    float ex = (lane < NCLS) ? __expf(lg - mx) : 0.f;
    float sm = ex;
    for (int o = 16; o > 0; o >>= 1) sm += __shfl_xor_sync(0xffffffffu, sm, o);
    if (lane < NCLS) out[row * NCLS + lane] = lg - mx - logf(sm);
}

// ---------------- launch ----------------
static inline void* sym(const void* s) {
    void* p = nullptr;
    cudaGetSymbolAddress(&p, s);
    return p;
}

extern "C" void kernel_launch(void* const* d_in, const int* in_sizes, int n_in,
                              void* d_out, int out_size) {
    const float* x        = (const float*)d_in[0];
    const int*   ei       = (const int*)d_in[1];
    const int*   batch    = (const int*)d_in[2];
    const float* bn_f_g   = (const float*)d_in[3];
    const float* bn_f_b   = (const float*)d_in[4];
    const float* w_feat   = (const float*)d_in[5];
    const float* b_feat   = (const float*)d_in[6];
    const float* bn_c_g   = (const float*)d_in[7];
    const float* bn_c_b   = (const float*)d_in[8];
    const float* w_gat    = (const float*)d_in[9];
    const float* att_l    = (const float*)d_in[10];
    const float* att_r    = (const float*)d_in[11];
    const float* b_gat    = (const float*)d_in[12];
    const float* bn_fc_g  = (const float*)d_in[13];
    const float* bn_fc_b  = (const float*)d_in[14];
    const float* w_fc     = (const float*)d_in[15];
    const float* b_fc     = (const float*)d_in[16];
    const float* bn_h_g   = (const float*)d_in[17];
    const float* bn_h_b   = (const float*)d_in[18];
    const float* w_cls    = (const float*)d_in[19];
    const float* b_cls    = (const float*)d_in[20];
    float* out = (float*)d_out;

    const int* srcp = ei;
    const int* dstp = ei + NEDGE;

    int*     deg    = (int*)sym(g_deg);
    int*     start  = (int*)sym(g_start);
    int*     cursor = (int*)sym(g_cursor);
    int*     bsum   = (int*)sym(g_bsum);
    int*     csr    = (int*)sym(g_csr);
    __half*  bufA   = (__half*)sym(g_bufA);
    __half*  bufB   = (__half*)sym(g_bufB);
    __half*  hh     = (__half*)sym(g_hh);
    float*   li     = (float*)sym(g_li);
    float*   ri     = (float*)sym(g_ri);
    __half*  Wh     = (__half*)sym(g_Wh);
    float*   Wf4    = (float*)sym(g_Wf4);
    float*   biasv  = (float*)sym(g_biasv);
    float*   pool   = (float*)sym(g_pool);
    float*   tmp    = (float*)sym(g_tmp);
    float*   Wct    = (float*)sym(g_Wct);
    float*   biasc  = (float*)sym(g_biasc);

    static cudaStream_t s2;
    static cudaEvent_t evFork, evJoin;
    static bool init_done = false;
    if (!init_done) {
        cudaFuncSetAttribute(k_gemm_tc<1, 0>, cudaFuncAttributeMaxDynamicSharedMemorySize,
                             GEMM_SMEM);
        cudaFuncSetAttribute(k_gemm_tc<0, 1>, cudaFuncAttributeMaxDynamicSharedMemorySize,
                             GEMM_SMEM);
        cudaStreamCreateWithFlags(&s2, cudaStreamNonBlocking);
        cudaEventCreateWithFlags(&evFork, cudaEventDisableTiming);
        cudaEventCreateWithFlags(&evJoin, cudaEventDisableTiming);
        init_done = true;
    }

    // fork: CSR build runs on s2, overlapping fold + feature GEMM + layer-0 EPI GEMM
    cudaEventRecord(evFork, 0);
    cudaStreamWaitEvent(s2, evFork, 0);
    k_csr<<<NB_SCAN, 1024, 0, s2>>>(srcp, dstp, deg, start, bsum, cursor, csr);
    cudaEventRecord(evJoin, s2);

    k_fold_all<<<1168, 128>>>(w_feat, bn_f_g, bn_f_b, b_feat,
                              w_gat, bn_c_g, bn_c_b,
                              w_fc, bn_fc_g, bn_fc_b, b_fc,
                              w_cls, bn_h_g, bn_h_b, b_cls,
                              Wh, Wf4, biasv, Wct, biasc, pool, out, out_size);

    int gblocks = GEMM_GRID < NT_GEMM ? GEMM_GRID : NT_GEMM;
    k_gemm_tc<1, 0><<<gblocks, 256, GEMM_SMEM>>>(x, Wh, biasv, bufA,
                                                 nullptr, nullptr, nullptr, nullptr,
                                                 NNODE);

    __half* cur = bufA;
    __half* nxt = bufB;
    for (int i = 0; i < 3; i++) {
        int L = 1 + i;
        k_gemm_tc<0, 1><<<gblocks, 256, GEMM_SMEM>>>(cur, Wh + L * HID * HID,
                                                     biasv + L * HID, hh,
                                                     li, ri,
                                                     att_l + i * HID, att_r + i * HID,
                                                     NNODE);
        if (i == 0) cudaStreamWaitEvent(0, evJoin, 0);   // join CSR before first attention
        k_attn<<<(NNODE * 32 + 255) / 256, 256>>>(hh, start, csr, li, ri,
                                                  b_gat + i * HID, nxt);
        __half* t2 = cur; cur = nxt; nxt = t2;
    }

    k_pool<<<(NNODE + PCHUNK - 1) / PCHUNK, HID>>>(cur, batch, pool);

    k_gemm_fc<<<(NG + 7) / 8, HID>>>(pool, Wf4, biasv + 4 * HID, tmp, NG);

    k_final<<<NG, 32>>>(tmp, Wct, biasc, out);
}